// round 4
// baseline (speedup 1.0000x reference)
#include <cuda_runtime.h>
#include <cstdint>
#include <cstdio>

// Problem constants (fixed by the reference: V=250000, H=128, N=32768, K=256).
#define H_DIM   128
#define K_SAMP  256
#define MT      128
#define THREADS 512

// Scratch (__device__ globals; no allocation allowed).
__device__ int   g_is64;
__device__ float g_WsT[H_DIM * K_SAMP];   // [h][k]  (transposed gathered sample weights)
__device__ float g_cb[K_SAMP];            // bias[s] - noise_logits[s]
__device__ float g_partials[512];         // per-tile row sums (N up to 65536)

// ---- f32x2 packed helpers (Blackwell FFMA2 only reachable via PTX) ----
__device__ __forceinline__ unsigned long long pack2(float lo, float hi) {
    unsigned long long r;
    asm("mov.b64 %0, {%1, %2};" : "=l"(r)
        : "r"(__float_as_uint(lo)), "r"(__float_as_uint(hi)));
    return r;
}
__device__ __forceinline__ unsigned long long dup2(float a) {
    unsigned int u = __float_as_uint(a);
    unsigned long long r;
    asm("mov.b64 %0, {%1, %2};" : "=l"(r) : "r"(u), "r"(u));
    return r;
}
__device__ __forceinline__ void fma2(unsigned long long& d,
                                     unsigned long long a, unsigned long long b) {
    asm("fma.rn.f32x2 %0, %1, %2, %0;" : "+l"(d) : "l"(a), "l"(b));
}
__device__ __forceinline__ void unpack2(unsigned long long v, float& lo, float& hi) {
    unsigned int ulo, uhi;
    asm("mov.b64 {%0, %1}, %2;" : "=r"(ulo), "=r"(uhi) : "l"(v));
    lo = __uint_as_float(ulo);
    hi = __uint_as_float(uhi);
}

// ---- dtype detection: int64 arrays read as int32 show (value, 0) pairs ----
__global__ void k_detect(const void* __restrict__ targets) {
    if (threadIdx.x == 0) {
        const unsigned int* p = (const unsigned int*)targets;
        int ok = 1;
#pragma unroll
        for (int i = 0; i < 32; i++)
            if (p[2 * i + 1] != 0u) ok = 0;
        g_is64 = ok;
    }
}

// ---- gather sample weights (transposed) + combined bias/noise constant ----
__global__ void k_prep(const float* __restrict__ weight, const float* __restrict__ bias,
                       const float* __restrict__ nl, const void* __restrict__ samples) {
    int k = blockIdx.x;
    int h = threadIdx.x;
    long long s = g_is64 ? ((const long long*)samples)[k]
                         : (long long)((const int*)samples)[k];
    g_WsT[h * K_SAMP + k] = weight[(size_t)s * H_DIM + h];
    if (h == 0) g_cb[k] = bias[s] - nl[s];
}

// ---- main: noise GEMM (f32x2 register-tiled) + fused target dot + logsumexp ----
__global__ __launch_bounds__(THREADS, 1)
void k_main(const float* __restrict__ weight, const float* __restrict__ bias,
            const float* __restrict__ hiddens, const float* __restrict__ nl,
            const void* __restrict__ targets, int N, int nTiles) {
    extern __shared__ float smem[];
    float* Bt   = smem;                         // [H_DIM][K_SAMP]   128 KB
    float* As   = Bt + H_DIM * K_SAMP;          // [MT][H_DIM]        64 KB
    float* cbs  = As + MT * H_DIM;              // [K_SAMP]            1 KB
    float* wred = cbs + K_SAMP;                 // [16]

    const int tid  = threadIdx.x;
    const int tx   = tid & 31;
    const int ty   = tid >> 5;
    const int is64 = g_is64;

    // Load Bt + cbs once per CTA (coalesced gmem, conflict-free STS).
    {
        const float4* src = (const float4*)g_WsT;
        float4* dst = (float4*)Bt;
        for (int i = tid; i < H_DIM * K_SAMP / 4; i += THREADS) dst[i] = src[i];
        for (int i = tid; i < K_SAMP; i += THREADS) cbs[i] = g_cb[i];
    }

    int r[8];
#pragma unroll
    for (int j = 0; j < 8; j++) r[j] = ty * 4 + (j & 3) + (j >> 2) * 64;

    for (int tile = blockIdx.x; tile < nTiles; tile += gridDim.x) {
        const int row0 = tile * MT;
        __syncthreads();   // protect As / wred from previous tile's readers

        // Load hiddens tile into As (row-major, float4-coalesced).
        {
            float4* dst = (float4*)As;
            for (int i = tid; i < MT * H_DIM / 4; i += THREADS) {
                int rr  = i >> 5;           // H_DIM/4 = 32 float4 per row
                int row = row0 + rr;
                float4 v = make_float4(0.f, 0.f, 0.f, 0.f);
                if (row < N)
                    v = ((const float4*)hiddens)[(size_t)row * (H_DIM / 4) + (i & 31)];
                dst[i] = v;
            }
        }
        __syncthreads();

        // 8x8 register tile per thread, f32x2-packed along columns.
        unsigned long long acc[8][4];
#pragma unroll
        for (int j = 0; j < 8; j++)
#pragma unroll
            for (int p = 0; p < 4; p++) acc[j][p] = 0ull;

#pragma unroll 8
        for (int h = 0; h < H_DIM; h++) {
            const float4 b0 = *(const float4*)&Bt[h * K_SAMP + tx * 4];
            const float4 b1 = *(const float4*)&Bt[h * K_SAMP + 128 + tx * 4];
            unsigned long long bp0 = pack2(b0.x, b0.y);
            unsigned long long bp1 = pack2(b0.z, b0.w);
            unsigned long long bp2 = pack2(b1.x, b1.y);
            unsigned long long bp3 = pack2(b1.z, b1.w);
#pragma unroll
            for (int j = 0; j < 8; j++) {
                unsigned long long ad = dup2(As[r[j] * H_DIM + h]);
                fma2(acc[j][0], ad, bp0);
                fma2(acc[j][1], ad, bp1);
                fma2(acc[j][2], ad, bp2);
                fma2(acc[j][3], ad, bp3);
            }
        }

        // Target logits for this warp's 8 rows (coalesced gather of weight row).
        float tl[8];
#pragma unroll
        for (int j = 0; j < 8; j++) {
            int row = row0 + r[j];
            float tlv = 0.f;
            if (row < N) {
                long long t = is64 ? ((const long long*)targets)[row]
                                   : (long long)((const int*)targets)[row];
                float4 wv = ((const float4*)weight)[(size_t)t * (H_DIM / 4) + tx];
                float4 hv = ((const float4*)As)[r[j] * (H_DIM / 4) + tx];
                float d = wv.x * hv.x + wv.y * hv.y + wv.z * hv.z + wv.w * hv.w;
#pragma unroll
                for (int o = 16; o > 0; o >>= 1)
                    d += __shfl_xor_sync(0xffffffffu, d, o);
                tlv = d + __ldg(&bias[t]) - __ldg(&nl[t]);
            }
            tl[j] = tlv;
        }

        float cbl[8];
#pragma unroll
        for (int q = 0; q < 4; q++) {
            cbl[q]     = cbs[tx * 4 + q];
            cbl[4 + q] = cbs[128 + tx * 4 + q];
        }

        // Stable logsumexp(G=2) per row; warp = one row group (8 rows x 256 cols).
        float rowsum = 0.f;
#pragma unroll
        for (int j = 0; j < 8; j++) {
            int row = row0 + r[j];
            float v[8];
            unpack2(acc[j][0], v[0], v[1]);
            unpack2(acc[j][1], v[2], v[3]);
            unpack2(acc[j][2], v[4], v[5]);
            unpack2(acc[j][3], v[6], v[7]);
#pragma unroll
            for (int q = 0; q < 8; q++) v[q] += cbl[q];

            float m = tl[j];
#pragma unroll
            for (int q = 0; q < 8; q++) m = fmaxf(m, v[q]);
#pragma unroll
            for (int o = 16; o > 0; o >>= 1)
                m = fmaxf(m, __shfl_xor_sync(0xffffffffu, m, o));

            float s = 0.f;
#pragma unroll
            for (int q = 0; q < 8; q++) s += __expf(2.f * (v[q] - m));
#pragma unroll
            for (int o = 16; o > 0; o >>= 1)
                s += __shfl_xor_sync(0xffffffffu, s, o);
            s += __expf(2.f * (tl[j] - m));   // target column, added once (lane-uniform)

            if (row < N) rowsum += tl[j] - (m + 0.5f * logf(s));
        }

        if (tx == 0) wred[ty] = rowsum;       // rowsum is lane-uniform
        __syncthreads();
        if (tid == 0) {
            float p = 0.f;
#pragma unroll
            for (int w = 0; w < 16; w++) p += wred[w];
            g_partials[tile] = p;             // deterministic per-tile partial
        }
    }
}

// ---- deterministic final reduction ----
__global__ void k_final(float* __restrict__ out, int N, int nTiles) {
    __shared__ float red[256];
    int tid = threadIdx.x;
    float v = 0.f;
    for (int t = tid; t < nTiles; t += 256) v += g_partials[t];
    red[tid] = v;
    __syncthreads();
#pragma unroll
    for (int s = 128; s > 0; s >>= 1) {
        if (tid < s) red[tid] += red[tid + s];
        __syncthreads();
    }
    if (tid == 0) out[0] = -red[0] / (float)N;
}

extern "C" void kernel_launch(void* const* d_in, const int* in_sizes, int n_in,
                              void* d_out, int out_size) {
    const float* weight  = (const float*)d_in[0];
    const float* bias    = (const float*)d_in[1];
    const float* hiddens = (const float*)d_in[2];
    const float* nl      = (const float*)d_in[3];
    const void*  targets = d_in[4];
    const void*  samples = d_in[5];
    (void)n_in; (void)out_size;

    const int N = in_sizes[4];
    const int nTiles = (N + MT - 1) / MT;
    const int grid = nTiles < 128 ? nTiles : 128;
    const size_t smem = (size_t)(H_DIM * K_SAMP + MT * H_DIM + K_SAMP + 16) * sizeof(float);

    // Idempotent, not a stream op — safe under graph capture.
    cudaFuncSetAttribute(k_main, cudaFuncAttributeMaxDynamicSharedMemorySize, (int)smem);

    k_detect<<<1, 32>>>(targets);
    k_prep<<<K_SAMP, H_DIM>>>(weight, bias, nl, samples);
    k_main<<<grid, THREADS, smem>>>(weight, bias, hiddens, nl, targets, N, nTiles);
    k_final<<<1, 256>>>((float*)d_out, N, nTiles);
}

// round 7
// speedup vs baseline: 2.4513x; 2.4513x over previous
#include <cuda_runtime.h>
#include <cuda_bf16.h>
#include <cstdint>

// Problem constants (V=250000, H=128, N=32768, K=256).
#define HD      128
#define KS      256
#define MT      128
#define THREADS 512
#define LDBE    136              // padded row stride (bf16 elems): conflict-free ldmatrix
#define ROWB    (LDBE * 2)       // 272 bytes per row

// ---------------- smem layout (bytes) ----------------
#define OFF_A    0                        // A tile 128 x 136 bf16  (34816 B)
#define OFF_B    (MT * ROWB)              // B tile 256 x 136 bf16  (69632 B)
#define OFF_CBS  (OFF_B + KS * ROWB)      // float[256]
#define OFF_TL   (OFF_CBS + 1024)         // float[128]
#define OFF_RM   (OFF_TL + 512)           // float[128*4] per-(row,nwarp) max
#define OFF_RS   (OFF_RM + 2048)          // float[128*4] per-(row,nwarp) sumexp
#define OFF_RED  (OFF_RS + 2048)          // float[512] final tree
#define OFF_WRD  (OFF_RED + 2048)         // float[4]
#define OFF_LAST (OFF_WRD + 16)           // int
#define SMEM_TOTAL (OFF_LAST + 16)

// ---------------- device globals (no allocation allowed) ----------------
__device__ int          g_is64;
__device__ float        g_cb[KS];                // bias[s] - noise_logits[s]
__device__ uint4        g_WsB[KS * HD / 8];      // gathered sample weights, bf16 [256][128]
__device__ float        g_partials[256];
__device__ unsigned int g_done;

// ---------------- helpers ----------------
__device__ __forceinline__ uint32_t smem_u32(const void* p) {
    uint32_t a;
    asm("{ .reg .u64 t; cvta.to.shared.u64 t, %1; cvt.u32.u64 %0, t; }" : "=r"(a) : "l"(p));
    return a;
}
__device__ __forceinline__ unsigned pk(float lo, float hi) {
    __nv_bfloat162 t = __floats2bfloat162_rn(lo, hi);
    return *reinterpret_cast<unsigned*>(&t);
}
#define LDSM4(r, a) \
    asm volatile("ldmatrix.sync.aligned.m8n8.x4.shared.b16 {%0,%1,%2,%3}, [%4];" \
        : "=r"((r)[0]), "=r"((r)[1]), "=r"((r)[2]), "=r"((r)[3]) : "r"(a))
__device__ __forceinline__ void mma_bf16(float* d, const uint32_t* a,
                                         uint32_t b0, uint32_t b1) {
    asm volatile("mma.sync.aligned.m16n8k16.row.col.f32.bf16.bf16.f32 "
                 "{%0,%1,%2,%3}, {%4,%5,%6,%7}, {%8,%9}, {%0,%1,%2,%3};"
                 : "+f"(d[0]), "+f"(d[1]), "+f"(d[2]), "+f"(d[3])
                 : "r"(a[0]), "r"(a[1]), "r"(a[2]), "r"(a[3]), "r"(b0), "r"(b1));
}

// ---------------- dtype detection (int64 read as int32 pairs -> hi words 0) ----
__global__ void k_detect(const void* __restrict__ targets) {
    if (threadIdx.x == 0) {
        const unsigned* p = (const unsigned*)targets;
        int ok = 1;
#pragma unroll
        for (int i = 0; i < 32; i++)
            if (p[2 * i + 1] != 0u) ok = 0;
        g_is64 = ok;
    }
}

// ---------------- gather sample weights -> bf16 B image + cb ----------------
__global__ void k_prep_w(const float* __restrict__ w, const float* __restrict__ bias,
                         const float* __restrict__ nl, const void* __restrict__ samples) {
    int i = blockIdx.x * 256 + threadIdx.x;          // 4096 chunks of 8 elems
    if (i >= KS * HD / 8) return;
    int n = i >> 4, k0 = (i & 15) << 3;
    long long s = g_is64 ? ((const long long*)samples)[n]
                         : (long long)((const int*)samples)[n];
    const float4* wr = (const float4*)(w + (size_t)s * HD);
    float4 a = wr[k0 >> 2], b = wr[(k0 >> 2) + 1];
    g_WsB[i] = make_uint4(pk(a.x, a.y), pk(a.z, a.w), pk(b.x, b.y), pk(b.z, b.w));
    if ((i & 15) == 0) g_cb[n] = bias[s] - nl[s];
}

// ---------------- main: mma.sync GEMM + fused target dot + logsumexp + final ----
__global__ __launch_bounds__(THREADS, 1)
void k_main(const float* __restrict__ weight, const float* __restrict__ bias,
            const float* __restrict__ nl, const void* __restrict__ targets,
            const float* __restrict__ hiddens, float* __restrict__ out, int N) {
    extern __shared__ __align__(16) char smem[];
    const int tid = threadIdx.x, w = tid >> 5, lane = tid & 31;
    const int tile = blockIdx.x, row0 = tile << 7;
    const uint32_t sb = smem_u32(smem);
    float* cbs = (float*)(smem + OFF_CBS);
    float* tl  = (float*)(smem + OFF_TL);
    float* rm  = (float*)(smem + OFF_RM);
    float* rs  = (float*)(smem + OFF_RS);
    float* red = (float*)(smem + OFF_RED);
    float* wrd = (float*)(smem + OFF_WRD);
    int*  last = (int*)(smem + OFF_LAST);

    // Fill A: fp32 hiddens -> bf16, padded rows.
    for (int i = tid; i < MT * HD / 4; i += THREADS) {     // 4096 float4 chunks
        int r = i >> 5, c4 = i & 31;
        float4 v = ((const float4*)hiddens)[(size_t)(row0 + r) * 32 + c4];
        uint2 o = make_uint2(pk(v.x, v.y), pk(v.z, v.w));
        *(uint2*)(smem + OFF_A + r * ROWB + c4 * 8) = o;
    }
    // Fill B (prepped bf16, L2-resident), padded rows.
    for (int i = tid; i < KS * HD / 8; i += THREADS) {     // 4096 uint4 chunks
        int r = i >> 4, c = i & 15;
        *(uint4*)(smem + OFF_B + r * ROWB + c * 16) = g_WsB[i];
    }
    if (tid < KS) cbs[tid] = g_cb[tid];
    if (tid == 0) *last = 0;
    __syncthreads();

    // Target logits (fp32): warp w -> rows w*8 .. w*8+7. hiddens rows are L1-hot.
    const int is64 = g_is64;
#pragma unroll
    for (int j = 0; j < 8; j++) {
        int m = w * 8 + j, row = row0 + m;
        long long t = is64 ? ((const long long*)targets)[row]
                           : (long long)((const int*)targets)[row];
        float4 hv = ((const float4*)hiddens)[(size_t)row * 32 + lane];
        float4 wv = ((const float4*)weight)[(size_t)t * 32 + lane];
        float d = hv.x * wv.x + hv.y * wv.y + hv.z * wv.z + hv.w * wv.w;
#pragma unroll
        for (int o = 16; o; o >>= 1) d += __shfl_xor_sync(0xffffffffu, d, o);
        if (lane == 0) tl[m] = d + __ldg(bias + t) - __ldg(nl + t);
    }

    // Mainloop: warp tile 32(m) x 64(n), K=128 in 8 steps of 16.
    const int bm = (w & 3) * 32, bn = (w >> 2) * 64;
    float d[2][8][4];
#pragma unroll
    for (int mf = 0; mf < 2; mf++)
#pragma unroll
        for (int nf = 0; nf < 8; nf++)
#pragma unroll
            for (int q = 0; q < 4; q++) d[mf][nf][q] = 0.f;

    const uint32_t aB = sb + OFF_A + (bm + (lane & 15)) * ROWB + ((lane >> 4) << 4);
    const uint32_t bB = sb + OFF_B + (bn + (lane & 15)) * ROWB + ((lane >> 4) << 4);
#pragma unroll
    for (int ks = 0; ks < 8; ks++) {
        const uint32_t off = ks * 32;
        uint32_t a[2][4], bb[4][4];
        LDSM4(a[0], aB + off);
        LDSM4(a[1], aB + 16 * ROWB + off);
#pragma unroll
        for (int q = 0; q < 4; q++) LDSM4(bb[q], bB + q * 16 * ROWB + off);
#pragma unroll
        for (int mf = 0; mf < 2; mf++)
#pragma unroll
            for (int nf = 0; nf < 8; nf++)
                mma_bf16(d[mf][nf], a[mf], bb[nf >> 1][nf & 1], bb[nf >> 1][(nf & 1) + 2]);
    }

    // Epilogue: per-row max/sumexp over this warp's 64 columns.
    const int g = lane >> 2, t4 = lane & 3;
    float2 cbl[8];
#pragma unroll
    for (int nf = 0; nf < 8; nf++)
        cbl[nf] = *(const float2*)&cbs[bn + nf * 8 + t4 * 2];
#pragma unroll
    for (int mf = 0; mf < 2; mf++)
#pragma unroll
        for (int h = 0; h < 2; h++) {
            int row = bm + mf * 16 + h * 8 + g;
            float vv[16], mx = -1e30f;
#pragma unroll
            for (int nf = 0; nf < 8; nf++) {
                vv[nf * 2]     = d[mf][nf][h * 2]     + cbl[nf].x;
                vv[nf * 2 + 1] = d[mf][nf][h * 2 + 1] + cbl[nf].y;
                mx = fmaxf(mx, fmaxf(vv[nf * 2], vv[nf * 2 + 1]));
            }
            mx = fmaxf(mx, __shfl_xor_sync(0xffffffffu, mx, 1));
            mx = fmaxf(mx, __shfl_xor_sync(0xffffffffu, mx, 2));
            float s = 0.f;
#pragma unroll
            for (int q = 0; q < 16; q++) s += __expf(2.f * (vv[q] - mx));
            s += __shfl_xor_sync(0xffffffffu, s, 1);
            s += __shfl_xor_sync(0xffffffffu, s, 2);
            if (t4 == 0) { rm[row * 4 + (w >> 2)] = mx; rs[row * 4 + (w >> 2)] = s; }
        }
    __syncthreads();

    // Merge 4 n-warp partials + target column per row; reduce deterministically.
    if (w < 4) {
        int row = w * 32 + lane;
        float t = tl[row];
        float m0 = rm[row * 4], m1 = rm[row * 4 + 1], m2 = rm[row * 4 + 2], m3 = rm[row * 4 + 3];
        float M = fmaxf(fmaxf(fmaxf(m0, m1), fmaxf(m2, m3)), t);
        float S = rs[row * 4]     * __expf(2.f * (m0 - M))
                + rs[row * 4 + 1] * __expf(2.f * (m1 - M))
                + rs[row * 4 + 2] * __expf(2.f * (m2 - M))
                + rs[row * 4 + 3] * __expf(2.f * (m3 - M))
                + __expf(2.f * (t - M));
        float res = t - (M + 0.5f * logf(S));
#pragma unroll
        for (int o = 16; o; o >>= 1) res += __shfl_xor_sync(0xffffffffu, res, o);
        if (lane == 0) wrd[w] = res;
    }
    __syncthreads();
    if (tid == 0) {
        g_partials[tile] = wrd[0] + wrd[1] + wrd[2] + wrd[3];
        __threadfence();
        unsigned prev = atomicAdd(&g_done, 1u);
        *last = (prev == gridDim.x - 1) ? 1 : 0;
    }
    __syncthreads();

    // Last CTA: deterministic fixed-order final reduction; reset counter.
    if (*last) {
        __threadfence();
        float v = 0.f;
        for (int i = tid; i < (int)gridDim.x; i += THREADS) v += g_partials[i];
        red[tid] = v;
        __syncthreads();
#pragma unroll
        for (int s = 256; s > 0; s >>= 1) {
            if (tid < s) red[tid] += red[tid + s];
            __syncthreads();
        }
        if (tid == 0) { out[0] = -red[0] / (float)N; g_done = 0u; }
    }
}

extern "C" void kernel_launch(void* const* d_in, const int* in_sizes, int n_in,
                              void* d_out, int out_size) {
    const float* weight  = (const float*)d_in[0];
    const float* bias    = (const float*)d_in[1];
    const float* hiddens = (const float*)d_in[2];
    const float* nl      = (const float*)d_in[3];
    const void*  targets = d_in[4];
    const void*  samples = d_in[5];
    (void)n_in; (void)out_size;

    const int N = in_sizes[4];          // 32768
    const int nTiles = N / MT;          // 256

    cudaFuncSetAttribute(k_main, cudaFuncAttributeMaxDynamicSharedMemorySize, SMEM_TOTAL);

    k_detect<<<1, 32>>>(targets);
    k_prep_w<<<16, 256>>>(weight, bias, nl, samples);
    k_main<<<nTiles, THREADS, SMEM_TOTAL>>>(weight, bias, nl, targets, hiddens,
                                            (float*)d_out, N);
}

// round 10
// speedup vs baseline: 3.0485x; 1.2436x over previous
#include <cuda_runtime.h>
#include <cuda_bf16.h>
#include <cstdint>

// Problem constants (V=250000, H=128, N=32768, K=256).
#define HD      128
#define KS      256
#define MT      128
#define THREADS 512
#define GRID    128
#define LDBE    136              // padded row stride (bf16 elems): conflict-free ldmatrix
#define ROWB    (LDBE * 2)       // 272 bytes per row

// ---------------- smem layout (bytes) ----------------
#define OFF_B    0                        // B tile 256 x 136 bf16   (69632 B)
#define OFF_A    69632                    // A tile 128 x 136 bf16   (34816 B)
#define OFF_STG  104448                   // fp32 staging 128x128    (65536 B)
#define OFF_CBS  169984                   // float[256]
#define OFF_TL   171008                   // float[128]
#define OFF_RM   171520                   // float[128*4]
#define OFF_RS   173568                   // float[128*4]
#define OFF_RED  175616                   // float[512]
#define OFF_WRD  177664                   // float[4]
#define OFF_LAST 177680                   // int
#define SMEM_TOTAL 177696

// ---------------- device globals (no allocation allowed) ----------------
__device__ float        g_partials[256];
__device__ unsigned int g_done;

// ---------------- helpers ----------------
__device__ __forceinline__ uint32_t smem_u32(const void* p) {
    uint32_t a;
    asm("{ .reg .u64 t; cvta.to.shared.u64 t, %1; cvt.u32.u64 %0, t; }" : "=r"(a) : "l"(p));
    return a;
}
__device__ __forceinline__ unsigned pk(float lo, float hi) {
    __nv_bfloat162 t = __floats2bfloat162_rn(lo, hi);
    return *reinterpret_cast<unsigned*>(&t);
}
#define LDSM4(r, a) \
    asm volatile("ldmatrix.sync.aligned.m8n8.x4.shared.b16 {%0,%1,%2,%3}, [%4];" \
        : "=r"((r)[0]), "=r"((r)[1]), "=r"((r)[2]), "=r"((r)[3]) : "r"(a))
__device__ __forceinline__ void mma_bf16(float* d, const uint32_t* a,
                                         uint32_t b0, uint32_t b1) {
    asm volatile("mma.sync.aligned.m16n8k16.row.col.f32.bf16.bf16.f32 "
                 "{%0,%1,%2,%3}, {%4,%5,%6,%7}, {%8,%9}, {%0,%1,%2,%3};"
                 : "+f"(d[0]), "+f"(d[1]), "+f"(d[2]), "+f"(d[3])
                 : "r"(a[0]), "r"(a[1]), "r"(a[2]), "r"(a[3]), "r"(b0), "r"(b1));
}
#define CP16(sa, gp) \
    asm volatile("cp.async.cg.shared.global [%0], [%1], 16;" :: "r"(sa), "l"(gp) : "memory")
#define CP_COMMIT() asm volatile("cp.async.commit_group;" ::: "memory")
#define CP_WAIT0()  asm volatile("cp.async.wait_group 0;" ::: "memory")

// int64-vs-int32 detection: int64 indices (<2^32) have all hi-words zero.
__device__ __forceinline__ int detect64(const void* idx, int lane) {
    unsigned hi = ((const unsigned*)idx)[2 * lane + 1];
    return __all_sync(0xffffffffu, hi == 0u);
}

// ---------------- single fused kernel ----------------
__global__ __launch_bounds__(THREADS, 1)
void k_all(const float* __restrict__ weight, const float* __restrict__ bias,
           const float* __restrict__ hiddens, const float* __restrict__ nl,
           const void* __restrict__ targets, const void* __restrict__ samples,
           float* __restrict__ out, int N, int nTiles) {
    extern __shared__ __align__(16) char smem[];
    const int tid = threadIdx.x, w = tid >> 5, lane = tid & 31;
    const uint32_t sb = smem_u32(smem);
    float* cbs = (float*)(smem + OFF_CBS);
    float* tl  = (float*)(smem + OFF_TL);
    float* rm  = (float*)(smem + OFF_RM);
    float* rs  = (float*)(smem + OFF_RS);
    float* red = (float*)(smem + OFF_RED);
    float* wrd = (float*)(smem + OFF_WRD);
    int*  last = (int*)(smem + OFF_LAST);

    const int is64_t = detect64(targets, lane);   // warp-uniform, no sync needed
    const int is64_s = detect64(samples, lane);

    // Prefetch first tile's A (fp32) into staging via cp.async.
    {
        const int row0 = blockIdx.x << 7;
        const float* src = hiddens + (size_t)row0 * HD;
#pragma unroll
        for (int it = 0; it < 8; it++) {
            int i = tid + it * THREADS;                 // 4096 float4 chunks
            CP16(sb + OFF_STG + i * 16, src + i * 4);
        }
        CP_COMMIT();
    }

    // Fill B: gather sample weight rows -> bf16 padded image (L2-hot after wave-front).
    for (int i = tid; i < KS * HD / 8; i += THREADS) {  // 4096 chunks of 8 elems
        int n = i >> 4, c = i & 15;
        long long s = is64_s ? ((const long long*)samples)[n]
                             : (long long)((const int*)samples)[n];
        const float4* wr = (const float4*)(weight + (size_t)s * HD);
        float4 a = wr[c * 2], b = wr[c * 2 + 1];
        *(uint4*)(smem + OFF_B + n * ROWB + c * 16) =
            make_uint4(pk(a.x, a.y), pk(a.z, a.w), pk(b.x, b.y), pk(b.z, b.w));
    }
    if (tid < KS) {
        long long s = is64_s ? ((const long long*)samples)[tid]
                             : (long long)((const int*)samples)[tid];
        cbs[tid] = bias[s] - nl[s];
    }
    if (tid == 0) *last = 0;

    for (int tile = blockIdx.x; tile < nTiles; tile += GRID) {
        const int row0 = tile << 7;

        // Staging ready -> convert fp32 staging to bf16 A image.
        CP_WAIT0();
        __syncthreads();
#pragma unroll
        for (int it = 0; it < 8; it++) {
            int i = tid + it * THREADS;
            int r = i >> 5, c4 = i & 31;
            float4 v = *(const float4*)(smem + OFF_STG + i * 16);
            *(uint2*)(smem + OFF_A + r * ROWB + c4 * 8) =
                make_uint2(pk(v.x, v.y), pk(v.z, v.w));
        }
        __syncthreads();

        // Kick off prefetch of the next tile's A while we compute this one.
        const int ntile = tile + GRID;
        if (ntile < nTiles) {
            const float* src = hiddens + ((size_t)ntile << 7) * HD;
#pragma unroll
            for (int it = 0; it < 8; it++) {
                int i = tid + it * THREADS;
                CP16(sb + OFF_STG + i * 16, src + i * 4);
            }
            CP_COMMIT();
        }

        // Target logits (fp32): warp w -> rows w*8 .. w*8+7.
#pragma unroll
        for (int j = 0; j < 8; j++) {
            int m = w * 8 + j, row = row0 + m;
            long long t = is64_t ? ((const long long*)targets)[row]
                                 : (long long)((const int*)targets)[row];
            float4 hv = ((const float4*)hiddens)[(size_t)row * 32 + lane];
            float4 wv = ((const float4*)weight)[(size_t)t * 32 + lane];
            float d = hv.x * wv.x + hv.y * wv.y + hv.z * wv.z + hv.w * wv.w;
#pragma unroll
            for (int o = 16; o; o >>= 1) d += __shfl_xor_sync(0xffffffffu, d, o);
            if (lane == 0) tl[m] = d + __ldg(bias + t) - __ldg(nl + t);
        }

        // Mainloop: warp tile 32(m) x 64(n), K=128 in 8 steps of 16.
        const int bm = (w & 3) * 32, bn = (w >> 2) * 64;
        float d[2][8][4];
#pragma unroll
        for (int mf = 0; mf < 2; mf++)
#pragma unroll
            for (int nf = 0; nf < 8; nf++)
#pragma unroll
                for (int q = 0; q < 4; q++) d[mf][nf][q] = 0.f;

        const uint32_t aB = sb + OFF_A + (bm + (lane & 15)) * ROWB + ((lane >> 4) << 4);
        const uint32_t bB = sb + OFF_B + (bn + (lane & 15)) * ROWB + ((lane >> 4) << 4);
#pragma unroll
        for (int ks = 0; ks < 8; ks++) {
            const uint32_t off = ks * 32;
            uint32_t a[2][4], bb[4][4];
            LDSM4(a[0], aB + off);
            LDSM4(a[1], aB + 16 * ROWB + off);
#pragma unroll
            for (int q = 0; q < 4; q++) LDSM4(bb[q], bB + q * 16 * ROWB + off);
#pragma unroll
            for (int mf = 0; mf < 2; mf++)
#pragma unroll
                for (int nf = 0; nf < 8; nf++)
                    mma_bf16(d[mf][nf], a[mf], bb[nf >> 1][nf & 1],
                             bb[nf >> 1][(nf & 1) + 2]);
        }

        // Epilogue: per-row max/sumexp over this warp's 64 columns.
        const int g = lane >> 2, t4 = lane & 3;
        float2 cbl[8];
#pragma unroll
        for (int nf = 0; nf < 8; nf++)
            cbl[nf] = *(const float2*)&cbs[bn + nf * 8 + t4 * 2];
#pragma unroll
        for (int mf = 0; mf < 2; mf++)
#pragma unroll
            for (int h = 0; h < 2; h++) {
                int row = bm + mf * 16 + h * 8 + g;
                float vv[16], mx = -1e30f;
#pragma unroll
                for (int nf = 0; nf < 8; nf++) {
                    vv[nf * 2]     = d[mf][nf][h * 2]     + cbl[nf].x;
                    vv[nf * 2 + 1] = d[mf][nf][h * 2 + 1] + cbl[nf].y;
                    mx = fmaxf(mx, fmaxf(vv[nf * 2], vv[nf * 2 + 1]));
                }
                mx = fmaxf(mx, __shfl_xor_sync(0xffffffffu, mx, 1));
                mx = fmaxf(mx, __shfl_xor_sync(0xffffffffu, mx, 2));
                float s = 0.f;
#pragma unroll
                for (int q = 0; q < 16; q++) s += __expf(2.f * (vv[q] - mx));
                s += __shfl_xor_sync(0xffffffffu, s, 1);
                s += __shfl_xor_sync(0xffffffffu, s, 2);
                if (t4 == 0) { rm[row * 4 + (w >> 2)] = mx; rs[row * 4 + (w >> 2)] = s; }
            }
        __syncthreads();

        // Merge 4 n-warp partials + target column per row; fixed-order reduce.
        if (w < 4) {
            int row = w * 32 + lane;
            float t = tl[row];
            float m0 = rm[row * 4],     m1 = rm[row * 4 + 1];
            float m2 = rm[row * 4 + 2], m3 = rm[row * 4 + 3];
            float M = fmaxf(fmaxf(fmaxf(m0, m1), fmaxf(m2, m3)), t);
            float S = rs[row * 4]     * __expf(2.f * (m0 - M))
                    + rs[row * 4 + 1] * __expf(2.f * (m1 - M))
                    + rs[row * 4 + 2] * __expf(2.f * (m2 - M))
                    + rs[row * 4 + 3] * __expf(2.f * (m3 - M))
                    + __expf(2.f * (t - M));
            float res = t - (M + 0.5f * logf(S));
#pragma unroll
            for (int o = 16; o; o >>= 1) res += __shfl_xor_sync(0xffffffffu, res, o);
            if (lane == 0) wrd[w] = res;
        }
        __syncthreads();
        if (tid == 0)
            g_partials[tile] = wrd[0] + wrd[1] + wrd[2] + wrd[3];
        __syncthreads();   // protect tl/rm/rs/wrd before next iteration
    }

    // Completion counter; last CTA does the deterministic final reduction.
    if (tid == 0) {
        __threadfence();
        unsigned prev = atomicAdd(&g_done, 1u);
        *last = (prev == GRID - 1) ? 1 : 0;
    }
    __syncthreads();
    if (*last) {
        __threadfence();
        float v = 0.f;
        for (int i = tid; i < nTiles; i += THREADS) v += g_partials[i];
        red[tid] = v;
        __syncthreads();
#pragma unroll
        for (int s = 256; s > 0; s >>= 1) {
            if (tid < s) red[tid] += red[tid + s];
            __syncthreads();
        }
        if (tid == 0) { out[0] = -red[0] / (float)N; g_done = 0u; }
    }
}

extern "C" void kernel_launch(void* const* d_in, const int* in_sizes, int n_in,
                              void* d_out, int out_size) {
    const float* weight  = (const float*)d_in[0];
    const float* bias    = (const float*)d_in[1];
    const float* hiddens = (const float*)d_in[2];
    const float* nl      = (const float*)d_in[3];
    const void*  targets = d_in[4];
    const void*  samples = d_in[5];
    (void)n_in; (void)out_size;

    const int N = in_sizes[4];          // 32768
    const int nTiles = N / MT;          // 256

    cudaFuncSetAttribute(k_all, cudaFuncAttributeMaxDynamicSharedMemorySize, SMEM_TOTAL);

    k_all<<<GRID, THREADS, SMEM_TOTAL>>>(weight, bias, hiddens, nl, targets, samples,
                                         (float*)d_out, N, nTiles);
}

// round 13
// speedup vs baseline: 3.0524x; 1.0013x over previous
#include <cuda_runtime.h>
#include <cuda_bf16.h>
#include <cstdint>

// Problem constants (V=250000, H=128, N=32768, K=256).
#define HD      128
#define KS      256
#define MT      64               // rows per CTA tile (M-split for 2 CTAs/SM)
#define THREADS 256
#define GRID    256
#define LDBE    136              // padded row stride (bf16 elems): conflict-free ldmatrix
#define ROWB    (LDBE * 2)       // 272 bytes per row

// ---------------- smem layout (bytes) ----------------
#define OFF_B    0                        // B tile 256 x 136 bf16   (69632 B)
#define OFF_A    69632                    // A tile  64 x 136 bf16   (17408 B)
#define OFF_CBS  87040                    // float[256]
#define OFF_TL   88064                    // float[64]
#define OFF_RM   88320                    // float[64*4]
#define OFF_RS   89344                    // float[64*4]
#define OFF_RED  90368                    // float[256]
#define OFF_WRD  91392                    // float[2]
#define OFF_LAST 91400                    // int
#define SMEM_TOTAL 91408

// ---------------- device globals (no allocation allowed) ----------------
__device__ float        g_partials[GRID];
__device__ unsigned int g_done;

// ---------------- helpers ----------------
__device__ __forceinline__ uint32_t smem_u32(const void* p) {
    uint32_t a;
    asm("{ .reg .u64 t; cvta.to.shared.u64 t, %1; cvt.u32.u64 %0, t; }" : "=r"(a) : "l"(p));
    return a;
}
__device__ __forceinline__ unsigned pk(float lo, float hi) {
    __nv_bfloat162 t = __floats2bfloat162_rn(lo, hi);
    return *reinterpret_cast<unsigned*>(&t);
}
#define LDSM4(r, a) \
    asm volatile("ldmatrix.sync.aligned.m8n8.x4.shared.b16 {%0,%1,%2,%3}, [%4];" \
        : "=r"((r)[0]), "=r"((r)[1]), "=r"((r)[2]), "=r"((r)[3]) : "r"(a))
__device__ __forceinline__ void mma_bf16(float* d, const uint32_t* a,
                                         uint32_t b0, uint32_t b1) {
    asm volatile("mma.sync.aligned.m16n8k16.row.col.f32.bf16.bf16.f32 "
                 "{%0,%1,%2,%3}, {%4,%5,%6,%7}, {%8,%9}, {%0,%1,%2,%3};"
                 : "+f"(d[0]), "+f"(d[1]), "+f"(d[2]), "+f"(d[3])
                 : "r"(a[0]), "r"(a[1]), "r"(a[2]), "r"(a[3]), "r"(b0), "r"(b1));
}

// int64-vs-int32 detection: int64 indices (<2^32) have all hi-words zero.
__device__ __forceinline__ int detect64(const void* idx, int lane) {
    unsigned hi = ((const unsigned*)idx)[2 * lane + 1];
    return __all_sync(0xffffffffu, hi == 0u);
}

// ---------------- single fused kernel: 2 CTAs/SM, 2 tiles/CTA ----------------
__global__ __launch_bounds__(THREADS, 2)
void k_all(const float* __restrict__ weight, const float* __restrict__ bias,
           const float* __restrict__ hiddens, const float* __restrict__ nl,
           const void* __restrict__ targets, const void* __restrict__ samples,
           float* __restrict__ out, int N, int nTiles) {
    extern __shared__ __align__(16) char smem[];
    const int tid = threadIdx.x, w = tid >> 5, lane = tid & 31;
    const uint32_t sb = smem_u32(smem);
    float* cbs = (float*)(smem + OFF_CBS);
    float* tl  = (float*)(smem + OFF_TL);
    float* rm  = (float*)(smem + OFF_RM);
    float* rs  = (float*)(smem + OFF_RS);
    float* red = (float*)(smem + OFF_RED);
    float* wrd = (float*)(smem + OFF_WRD);
    int*  last = (int*)(smem + OFF_LAST);

    const int is64_t = detect64(targets, lane);   // warp-uniform, no sync needed
    const int is64_s = detect64(samples, lane);

    // Fill B once: gather sample weight rows -> bf16 padded image.
    for (int i = tid; i < KS * HD / 8; i += THREADS) {  // 4096 chunks of 8 elems
        int n = i >> 4, c = i & 15;
        long long s = is64_s ? ((const long long*)samples)[n]
                             : (long long)((const int*)samples)[n];
        const float4* wr = (const float4*)(weight + (size_t)s * HD);
        float4 a = wr[c * 2], b = wr[c * 2 + 1];
        *(uint4*)(smem + OFF_B + n * ROWB + c * 16) =
            make_uint4(pk(a.x, a.y), pk(a.z, a.w), pk(b.x, b.y), pk(b.z, b.w));
    }
    {
        long long s = is64_s ? ((const long long*)samples)[tid]
                             : (long long)((const int*)samples)[tid];
        cbs[tid] = bias[s] - nl[s];
    }
    if (tid == 0) *last = 0;

    float cta_part = 0.f;

    for (int tile = blockIdx.x; tile < nTiles; tile += GRID) {
        const int row0 = tile * MT;

        // Target logits first (long random-DRAM latency overlaps A fill below).
        // Warp w -> rows w*8 .. w*8+7 (64 rows, 8 warps).
#pragma unroll
        for (int j = 0; j < 8; j++) {
            int m = w * 8 + j, row = row0 + m;
            long long t = is64_t ? ((const long long*)targets)[row]
                                 : (long long)((const int*)targets)[row];
            float4 hv = ((const float4*)hiddens)[(size_t)row * 32 + lane];
            float4 wv = ((const float4*)weight)[(size_t)t * 32 + lane];
            float d = hv.x * wv.x + hv.y * wv.y + hv.z * wv.z + hv.w * wv.w;
#pragma unroll
            for (int o = 16; o; o >>= 1) d += __shfl_xor_sync(0xffffffffu, d, o);
            if (lane == 0) tl[m] = d + __ldg(bias + t) - __ldg(nl + t);
        }

        // A fill: fp32 hiddens -> bf16 padded image (64 rows).
#pragma unroll
        for (int it = 0; it < 8; it++) {
            int i = tid + it * THREADS;                 // 2048 float4 chunks
            int r = i >> 5, c4 = i & 31;
            float4 v = ((const float4*)hiddens)[((size_t)row0 + r) * 32 + c4];
            *(uint2*)(smem + OFF_A + r * ROWB + c4 * 8) =
                make_uint2(pk(v.x, v.y), pk(v.z, v.w));
        }
        __syncthreads();

        // Mainloop: warp tile 32(m) x 64(n), K=128 in 8 steps of 16.
        const int bm = (w & 1) * 32, bn = (w >> 1) * 64;
        float d[2][8][4];
#pragma unroll
        for (int mf = 0; mf < 2; mf++)
#pragma unroll
            for (int nf = 0; nf < 8; nf++)
#pragma unroll
                for (int q = 0; q < 4; q++) d[mf][nf][q] = 0.f;

        const uint32_t aB = sb + OFF_A + (bm + (lane & 15)) * ROWB + ((lane >> 4) << 4);
        const uint32_t bB = sb + OFF_B + (bn + (lane & 15)) * ROWB + ((lane >> 4) << 4);
#pragma unroll
        for (int ks = 0; ks < 8; ks++) {
            const uint32_t off = ks * 32;
            uint32_t a[2][4], bb[4][4];
            LDSM4(a[0], aB + off);
            LDSM4(a[1], aB + 16 * ROWB + off);
#pragma unroll
            for (int q = 0; q < 4; q++) LDSM4(bb[q], bB + q * 16 * ROWB + off);
#pragma unroll
            for (int mf = 0; mf < 2; mf++)
#pragma unroll
                for (int nf = 0; nf < 8; nf++)
                    mma_bf16(d[mf][nf], a[mf], bb[nf >> 1][nf & 1],
                             bb[nf >> 1][(nf & 1) + 2]);
        }

        // Epilogue: per-row max/sumexp over this warp's 64 columns.
        const int g = lane >> 2, t4 = lane & 3;
        float2 cbl[8];
#pragma unroll
        for (int nf = 0; nf < 8; nf++)
            cbl[nf] = *(const float2*)&cbs[bn + nf * 8 + t4 * 2];
#pragma unroll
        for (int mf = 0; mf < 2; mf++)
#pragma unroll
            for (int h = 0; h < 2; h++) {
                int row = bm + mf * 16 + h * 8 + g;
                float vv[16], mx = -1e30f;
#pragma unroll
                for (int nf = 0; nf < 8; nf++) {
                    vv[nf * 2]     = d[mf][nf][h * 2]     + cbl[nf].x;
                    vv[nf * 2 + 1] = d[mf][nf][h * 2 + 1] + cbl[nf].y;
                    mx = fmaxf(mx, fmaxf(vv[nf * 2], vv[nf * 2 + 1]));
                }
                mx = fmaxf(mx, __shfl_xor_sync(0xffffffffu, mx, 1));
                mx = fmaxf(mx, __shfl_xor_sync(0xffffffffu, mx, 2));
                float s = 0.f;
#pragma unroll
                for (int q = 0; q < 16; q++) s += __expf(2.f * (vv[q] - mx));
                s += __shfl_xor_sync(0xffffffffu, s, 1);
                s += __shfl_xor_sync(0xffffffffu, s, 2);
                if (t4 == 0) { rm[row * 4 + (w >> 1)] = mx; rs[row * 4 + (w >> 1)] = s; }
            }
        __syncthreads();

        // Merge 4 n-warp partials + target column per row; fixed-order reduce.
        if (w < 2) {
            int row = w * 32 + lane;
            float t = tl[row];
            float m0 = rm[row * 4],     m1 = rm[row * 4 + 1];
            float m2 = rm[row * 4 + 2], m3 = rm[row * 4 + 3];
            float M = fmaxf(fmaxf(fmaxf(m0, m1), fmaxf(m2, m3)), t);
            float S = rs[row * 4]     * __expf(2.f * (m0 - M))
                    + rs[row * 4 + 1] * __expf(2.f * (m1 - M))
                    + rs[row * 4 + 2] * __expf(2.f * (m2 - M))
                    + rs[row * 4 + 3] * __expf(2.f * (m3 - M))
                    + __expf(2.f * (t - M));
            float res = t - (M + 0.5f * logf(S));
#pragma unroll
            for (int o = 16; o; o >>= 1) res += __shfl_xor_sync(0xffffffffu, res, o);
            if (lane == 0) wrd[w] = res;
        }
        __syncthreads();
        if (tid == 0) cta_part += wrd[0] + wrd[1];
        // Next tile's writes to tl/rm/rs/wrd occur only after the next
        // epilogue barriers; tid0's read above is ordered by this sync path.
    }

    // Completion counter; last CTA does the deterministic final reduction.
    if (tid == 0) {
        g_partials[blockIdx.x] = cta_part;
        __threadfence();
        unsigned prev = atomicAdd(&g_done, 1u);
        *last = (prev == GRID - 1) ? 1 : 0;
    }
    __syncthreads();
    if (*last) {
        __threadfence();
        red[tid] = g_partials[tid];
        __syncthreads();
#pragma unroll
        for (int s = 128; s > 0; s >>= 1) {
            if (tid < s) red[tid] += red[tid + s];
            __syncthreads();
        }
        if (tid == 0) { out[0] = -red[0] / (float)N; g_done = 0u; }
    }
}

extern "C" void kernel_launch(void* const* d_in, const int* in_sizes, int n_in,
                              void* d_out, int out_size) {
    const float* weight  = (const float*)d_in[0];
    const float* bias    = (const float*)d_in[1];
    const float* hiddens = (const float*)d_in[2];
    const float* nl      = (const float*)d_in[3];
    const void*  targets = d_in[4];
    const void*  samples = d_in[5];
    (void)n_in; (void)out_size;

    const int N = in_sizes[4];          // 32768
    const int nTiles = N / MT;          // 512

    cudaFuncSetAttribute(k_all, cudaFuncAttributeMaxDynamicSharedMemorySize, SMEM_TOTAL);

    k_all<<<GRID, THREADS, SMEM_TOTAL>>>(weight, bias, hiddens, nl, targets, samples,
                                         (float*)d_out, N, nTiles);
}